// round 14
// baseline (speedup 1.0000x reference)
#include <cuda_runtime.h>
#include <cuda_bf16.h>
#include <math.h>
#include <stdint.h>

#define Dv    128
#define Mv    128
#define KTABv 64
#define Kv    32
#define Bv    2048
#define FEWv  5
#define DMv   256
#define HIDv  512
#define NSYMv 100000
#define NROWS (Bv + FEWv)     /* 2053 */
#define NUNIT (2*Bv + 2*FEWv) /* 4106 */
#define G4    1024            /* packed gate width: 4 gates x 256, interleaved 4j+g */
#define SMEM_MMA 30720        /* mainloop tiles (30.7KB) >= acc staging (16.9KB) */

// ---------------- scratch (device globals) ----------------------------------
__device__ float g_X [NROWS * DMv];
__device__ float g_O [NROWS * DMv];
__device__ float g_G0[(size_t)Bv * G4];
__device__ float g_C [Bv * DMv];
__device__ float g_h [Bv * DMv];
__device__ float g_sg [DMv];
__device__ float g_sgn[DMv];
__device__ float g_rt4[G4];
__device__ float g_b4[G4];
__device__ __nv_bfloat16 g_NAhi[(size_t)2 * NUNIT * DMv], g_NAlo[(size_t)2 * NUNIT * DMv];
__device__ __nv_bfloat16 g_XAhi[NROWS * DMv], g_XAlo[NROWS * DMv];
__device__ __nv_bfloat16 g_Hshi[(size_t)NROWS * HIDv], g_Hslo[(size_t)NROWS * HIDv];
__device__ __nv_bfloat16 g_Xhi[Bv * DMv], g_Xlo[Bv * DMv];
__device__ __nv_bfloat16 g_hhi[Bv * DMv], g_hlo[Bv * DMv];
__device__ __nv_bfloat16 g_WihHi[G4 * DMv], g_WihLo[G4 * DMv];
__device__ __nv_bfloat16 g_WhhHi[G4 * DMv], g_WhhLo[G4 * DMv];
__device__ __nv_bfloat16 g_WgcnHi[Dv * DMv], g_WgcnLo[Dv * DMv];
__device__ __nv_bfloat16 g_Wp1Hi[HIDv * DMv], g_Wp1Lo[HIDv * DMv];
__device__ __nv_bfloat16 g_Wp2Hi[DMv * HIDv], g_Wp2Lo[DMv * HIDv];

__device__ __forceinline__ float sigm(float x) { return 1.f / (1.f + expf(-x)); }

__device__ __forceinline__ uint32_t smem_u32(const void* p) {
    uint32_t a;
    asm("{ .reg .u64 t; cvta.to.shared.u64 t, %1; cvt.u32.u64 %0, t; }" : "=r"(a) : "l"(p));
    return a;
}
__device__ __forceinline__ void ldsm_x4(uint32_t* r, uint32_t addr) {
    asm volatile("ldmatrix.sync.aligned.m8n8.x4.shared.b16 {%0,%1,%2,%3}, [%4];"
        : "=r"(r[0]), "=r"(r[1]), "=r"(r[2]), "=r"(r[3]) : "r"(addr));
}

__device__ __forceinline__ void split_store4(float4 v, __nv_bfloat16* hi,
                                             __nv_bfloat16* lo, size_t idx)
{
    __nv_bfloat16 h0 = __float2bfloat16(v.x), h1 = __float2bfloat16(v.y);
    __nv_bfloat16 h2 = __float2bfloat16(v.z), h3 = __float2bfloat16(v.w);
    __nv_bfloat162 a, b, c, d;
    a.x = h0; a.y = h1; b.x = h2; b.y = h3;
    c.x = __float2bfloat16(v.x - __bfloat162float(h0));
    c.y = __float2bfloat16(v.y - __bfloat162float(h1));
    d.x = __float2bfloat16(v.z - __bfloat162float(h2));
    d.y = __float2bfloat16(v.w - __bfloat162float(h3));
    *(__nv_bfloat162*)&hi[idx]     = a;
    *(__nv_bfloat162*)&hi[idx + 2] = b;
    *(__nv_bfloat162*)&lo[idx]     = c;
    *(__nv_bfloat162*)&lo[idx + 2] = d;
}

// ================= pack gate weights (bf16 hi/lo, interleaved 4j+g) =========
__global__ void pack_w(const float* __restrict__ w_ih, const float* __restrict__ w_hh,
                       const float* __restrict__ b_ih, const float* __restrict__ b_hh)
{
    const int r = blockIdx.x, t = threadIdx.x;
    const int j = r >> 2, gate = r & 3;
    const int m = gate * 512 + j;
    float vih = w_ih[(size_t)m * DMv + t];
    __nv_bfloat16 h1 = __float2bfloat16(vih);
    g_WihHi[(size_t)r * DMv + t] = h1;
    g_WihLo[(size_t)r * DMv + t] = __float2bfloat16(vih - __bfloat162float(h1));
    float vhh = w_hh[(size_t)m * HIDv + t];
    __nv_bfloat16 h2 = __float2bfloat16(vhh);
    g_WhhHi[(size_t)r * DMv + t] = h2;
    g_WhhLo[(size_t)r * DMv + t] = __float2bfloat16(vhh - __bfloat162float(h2));
    if (t == 0) g_b4[r] = b_ih[m] + b_hh[m];
}

// ================= pack support-encoder + gcn weights ========================
__global__ void pack_se(const float* __restrict__ gcn_w, const float* __restrict__ p1_w,
                        const float* __restrict__ p2_w)
{
    const int r = blockIdx.x, t = threadIdx.x;
    if (r < Dv) {
        float v = gcn_w[(size_t)r * DMv + t];
        __nv_bfloat16 h = __float2bfloat16(v);
        g_WgcnHi[(size_t)r * DMv + t] = h;
        g_WgcnLo[(size_t)r * DMv + t] = __float2bfloat16(v - __bfloat162float(h));
    } else if (r < Dv + HIDv) {
        int q = r - Dv;
        float v = p1_w[(size_t)q * DMv + t];
        __nv_bfloat16 h = __float2bfloat16(v);
        g_Wp1Hi[(size_t)q * DMv + t] = h;
        g_Wp1Lo[(size_t)q * DMv + t] = __float2bfloat16(v - __bfloat162float(h));
    } else {
        int q = r - Dv - HIDv;
        #pragma unroll
        for (int s = 0; s < 2; ++s) {
            int c = t + s * 256;
            float v = p2_w[(size_t)q * HIDv + c];
            __nv_bfloat16 h = __float2bfloat16(v);
            g_Wp2Hi[(size_t)q * HIDv + c] = h;
            g_Wp2Lo[(size_t)q * HIDv + c] = __float2bfloat16(v - __bfloat162float(h));
        }
    }
}

// ================= neighbor encoder: sims + topk + means (float4) ===========
__global__ __launch_bounds__(256) void ne_sims(
    const int* __restrict__ query, const int* __restrict__ support,
    const int* __restrict__ q_l_conn, const int* __restrict__ q_r_conn,
    const int* __restrict__ s_l_conn, const int* __restrict__ s_r_conn,
    const int* __restrict__ knn, const float* __restrict__ emb)
{
    __shared__ float4 s_center4[32];
    __shared__ float4 s_pad4[32];
    __shared__ float  s_sims[Mv];
    __shared__ float  s_sims2[KTABv];
    __shared__ int    s_rel[Mv], s_ent[Mv], s_kid[KTABv];
    __shared__ int    s_lst1[Kv], s_lst2[Kv];
    __shared__ float4 s_par[12][32];
    __shared__ float  s_cn;

    const int u   = blockIdx.x;
    const int tid = threadIdx.x;
    const int lane = tid & 31, w = tid >> 5;

    const int* conn; int id;
    if (u < Bv)            { conn = q_l_conn + (size_t)u * (Mv*2);            id = query[u*2+0]; }
    else if (u < 2*Bv)     { int v = u - Bv;    conn = q_r_conn + (size_t)v*(Mv*2); id = query[v*2+1]; }
    else if (u < 2*Bv+FEWv){ int v = u - 2*Bv;  conn = s_l_conn + (size_t)v*(Mv*2); id = support[v*2+0]; }
    else                   { int v = u - (2*Bv+FEWv); conn = s_r_conn + (size_t)v*(Mv*2); id = support[v*2+1]; }

    if (tid < 32) {
        float4 cv = __ldg((const float4*)(emb + (size_t)id * Dv) + tid);
        s_center4[tid] = cv;
        float v = cv.x*cv.x + cv.y*cv.y + cv.z*cv.z + cv.w*cv.w;
        #pragma unroll
        for (int o = 16; o; o >>= 1) v += __shfl_xor_sync(0xffffffffu, v, o);
        if (tid == 0) s_cn = sqrtf(v);
    } else if (tid < 64) {
        s_pad4[tid - 32] = __ldg((const float4*)(emb + (size_t)NSYMv * Dv) + (tid - 32));
    } else if (tid < 192) {
        int m = tid - 64;
        int2 rc = ((const int2*)conn)[m];
        s_rel[m] = rc.x; s_ent[m] = rc.y;
    } else {
        int m = tid - 192;
        s_kid[m] = knn[(size_t)id * KTABv + m];
    }
    __syncthreads();
    const float  cn = s_cn;
    const float4 c4 = s_center4[lane];

    #pragma unroll
    for (int i = 0; i < 16; i += 4) {
        float dt[4], nr[4];
        #pragma unroll
        for (int r = 0; r < 4; ++r) {
            int m = w * 16 + i + r;
            float4 x = __ldg((const float4*)(emb + (size_t)s_ent[m] * Dv) + lane);
            dt[r] = c4.x*x.x + c4.y*x.y + c4.z*x.z + c4.w*x.w;
            nr[r] = x.x*x.x + x.y*x.y + x.z*x.z + x.w*x.w;
        }
        #pragma unroll
        for (int o = 16; o; o >>= 1) {
            #pragma unroll
            for (int r = 0; r < 4; ++r) {
                dt[r] += __shfl_xor_sync(0xffffffffu, dt[r], o);
                nr[r] += __shfl_xor_sync(0xffffffffu, nr[r], o);
            }
        }
        if (lane == 0) {
            #pragma unroll
            for (int r = 0; r < 4; ++r)
                s_sims[w*16 + i + r] = dt[r] / fmaxf(cn * sqrtf(nr[r]), 1e-8f);
        }
    }
    #pragma unroll
    for (int i = 0; i < 8; i += 4) {
        float dt[4], nr[4];
        #pragma unroll
        for (int r = 0; r < 4; ++r) {
            int m = w * 8 + i + r;
            float4 x = __ldg((const float4*)(emb + (size_t)s_kid[m] * Dv) + lane);
            dt[r] = c4.x*x.x + c4.y*x.y + c4.z*x.z + c4.w*x.w;
            nr[r] = x.x*x.x + x.y*x.y + x.z*x.z + x.w*x.w;
        }
        #pragma unroll
        for (int o = 16; o; o >>= 1) {
            #pragma unroll
            for (int r = 0; r < 4; ++r) {
                dt[r] += __shfl_xor_sync(0xffffffffu, dt[r], o);
                nr[r] += __shfl_xor_sync(0xffffffffu, nr[r], o);
            }
        }
        if (lane == 0) {
            #pragma unroll
            for (int r = 0; r < 4; ++r)
                s_sims2[w*8 + i + r] = dt[r] / fmaxf(cn * sqrtf(nr[r]), 1e-8f);
        }
    }
    __syncthreads();

    if (tid < Mv) {
        float my = s_sims[tid];
        int cnt = 0;
        #pragma unroll 8
        for (int j = 0; j < Mv; ++j) {
            float o = s_sims[j];
            cnt += (o > my) || (o == my && j < tid);
        }
        if (cnt < Kv) s_lst1[cnt] = tid;
    } else if (tid < Mv + KTABv) {
        int m = tid - Mv;
        float my = s_sims2[m];
        int cnt = 0;
        #pragma unroll 8
        for (int j = 0; j < KTABv; ++j) {
            float o = s_sims2[j];
            cnt += (o > my) || (o == my && j < m);
        }
        if (cnt < Kv) s_lst2[cnt] = m;
    }
    __syncthreads();

    float4 a1 = make_float4(0.f,0.f,0.f,0.f), a2 = make_float4(0.f,0.f,0.f,0.f);
    if (w < 4) {
        #pragma unroll
        for (int e = 0; e < 8; ++e) {
            int m = s_lst1[w*8 + e];
            float4 xr = __ldg((const float4*)(emb + (size_t)s_rel[m] * Dv) + lane);
            float4 xe = __ldg((const float4*)(emb + (size_t)s_ent[m] * Dv) + lane);
            a1.x += xr.x; a1.y += xr.y; a1.z += xr.z; a1.w += xr.w;
            a2.x += xe.x; a2.y += xe.y; a2.z += xe.z; a2.w += xe.w;
        }
        s_par[w][lane] = a1;
        s_par[4 + w][lane] = a2;
    } else {
        #pragma unroll
        for (int e = 0; e < 8; ++e) {
            int m = s_lst2[(w-4)*8 + e];
            float4 xk = __ldg((const float4*)(emb + (size_t)s_kid[m] * Dv) + lane);
            a1.x += xk.x; a1.y += xk.y; a1.z += xk.z; a1.w += xk.w;
        }
        s_par[4 + w][lane] = a1;
    }
    __syncthreads();

    const float inv = 1.f / (float)Kv;
    if (w < 3) {
        int base = w * 4;
        float4 p0 = s_par[base+0][lane], p1 = s_par[base+1][lane];
        float4 p2 = s_par[base+2][lane], p3 = s_par[base+3][lane];
        float4 s;
        s.x = (p0.x + p1.x + p2.x + p3.x) * inv;
        s.y = (p0.y + p1.y + p2.y + p3.y) * inv;
        s.z = (p0.z + p1.z + p2.z + p3.z) * inv;
        s.w = (p0.w + p1.w + p2.w + p3.w) * inv;
        size_t off;
        if (w == 0)      off = (size_t)(2*u) * DMv;
        else if (w == 1) off = (size_t)(2*u) * DMv + Dv;
        else             off = (size_t)(2*u + 1) * DMv + Dv;
        split_store4(s, g_NAhi, g_NAlo, off + lane * 4);
    } else if (w == 3) {
        split_store4(s_pad4[lane], g_NAhi, g_NAlo, (size_t)(2*u + 1) * DMv + lane * 4);
    }
}

// ================= shared mma.sync bf16 3-split mainloop (ldmatrix) ==========
// 32x128 tile, 8 warps (1x8), warptile 32x16, K steps of 16.
// smem (bf16, row stride 24 = 48B): Ah buf*1536, Al 3072+buf*1536,
//   Bh 6144+buf*6144, Bl 18432+buf*6144.  Result -> sAcc [32][132] floats.
#define MMA16816(c, a, b) \
    asm volatile("mma.sync.aligned.m16n8k16.row.col.f32.bf16.bf16.f32 " \
        "{%0,%1,%2,%3}, {%4,%5,%6,%7}, {%8,%9}, {%0,%1,%2,%3};" \
        : "+f"((c)[0]), "+f"((c)[1]), "+f"((c)[2]), "+f"((c)[3]) \
        : "r"((a)[0]), "r"((a)[1]), "r"((a)[2]), "r"((a)[3]), "r"((b)[0]), "r"((b)[1]))

__device__ __forceinline__ void mma3s_main(
    char* sm,
    const __nv_bfloat16* __restrict__ Ahi, const __nv_bfloat16* __restrict__ Alo,
    int lda, int maxRow,
    const __nv_bfloat16* __restrict__ Whi, const __nv_bfloat16* __restrict__ Wlo,
    int ldb, int rowBase, int colBase, int nk)
{
    const int tid = threadIdx.x;
    const int lane = tid & 31, wc = tid >> 5;   // warp = column group 0..7
    const uint32_t sbase = smem_u32(sm);

    float acc[2][2][4];
    #pragma unroll
    for (int mi = 0; mi < 2; ++mi)
        #pragma unroll
        for (int ni = 0; ni < 2; ++ni)
            #pragma unroll
            for (int q = 0; q < 4; ++q) acc[mi][ni][q] = 0.f;

    // A loader: 32 rows x 16 k x 2 splits; one uint2 per thread
    const int arow = tid >> 3, aq = tid & 7;
    const int asplit = aq >> 2, ak = (aq & 3) * 4;
    const int aRowG = min(rowBase + arow, maxRow);
    const __nv_bfloat16* Asrc = asplit ? Alo : Ahi;
    const int aDst = asplit * 3072;
    const int aOff = (arow * 24 + ak) * 2;
    // B loader: 128 rows x 16 k x 2 splits; four uint2 per thread
    const int brow = tid >> 2, bk = (tid & 3) * 4;
    const int bOff = (brow * 24 + bk) * 2;
    const int bOff2 = ((64 + brow) * 24 + bk) * 2;

    // ldmatrix lane addressing
    const int lp = lane >> 3, lq = lane & 7;
    const int aRowSel = (lp & 1) * 8 + lq, aKSel = (lp >> 1) * 8;
    const int bRowSel = (lp >> 1) * 8 + lq, bKSel = (lp & 1) * 8;

    {
        uint2 vA = *(const uint2*)(Asrc + (size_t)aRowG * lda + ak);
        uint2 vBh0 = *(const uint2*)(Whi + (size_t)(colBase + brow) * ldb + bk);
        uint2 vBh1 = *(const uint2*)(Whi + (size_t)(colBase + 64 + brow) * ldb + bk);
        uint2 vBl0 = *(const uint2*)(Wlo + (size_t)(colBase + brow) * ldb + bk);
        uint2 vBl1 = *(const uint2*)(Wlo + (size_t)(colBase + 64 + brow) * ldb + bk);
        *(uint2*)(sm + aDst + aOff) = vA;
        *(uint2*)(sm + 6144  + bOff)  = vBh0;
        *(uint2*)(sm + 6144  + bOff2) = vBh1;
        *(uint2*)(sm + 18432 + bOff)  = vBl0;
        *(uint2*)(sm + 18432 + bOff2) = vBl1;
    }
    __syncthreads();

    int buf = 0;
    uint2 vA, vBh0, vBh1, vBl0, vBl1;
    for (int it = 0; it < nk; ++it) {
        if (it < nk - 1) {
            int k0 = (it + 1) * 16;
            vA = *(const uint2*)(Asrc + (size_t)aRowG * lda + k0 + ak);
            vBh0 = *(const uint2*)(Whi + (size_t)(colBase + brow) * ldb + k0 + bk);
            vBh1 = *(const uint2*)(Whi + (size_t)(colBase + 64 + brow) * ldb + k0 + bk);
            vBl0 = *(const uint2*)(Wlo + (size_t)(colBase + brow) * ldb + k0 + bk);
            vBl1 = *(const uint2*)(Wlo + (size_t)(colBase + 64 + brow) * ldb + k0 + bk);
        }
        {
            const uint32_t aH = sbase + buf * 1536;
            const uint32_t aL = sbase + 3072 + buf * 1536;
            const uint32_t bH = sbase + 6144 + buf * 6144;
            const uint32_t bL = sbase + 18432 + buf * 6144;
            uint32_t ah[2][4], al[2][4], bh[2][2], bl[2][2];
            #pragma unroll
            for (int mi = 0; mi < 2; ++mi) {
                uint32_t off = ((mi * 16 + aRowSel) * 24 + aKSel) * 2;
                ldsm_x4(ah[mi], aH + off);
                ldsm_x4(al[mi], aL + off);
            }
            {
                uint32_t off = ((wc * 16 + bRowSel) * 24 + bKSel) * 2;
                uint32_t rh[4], rl[4];
                ldsm_x4(rh, bH + off);
                ldsm_x4(rl, bL + off);
                bh[0][0] = rh[0]; bh[0][1] = rh[1];
                bh[1][0] = rh[2]; bh[1][1] = rh[3];
                bl[0][0] = rl[0]; bl[0][1] = rl[1];
                bl[1][0] = rl[2]; bl[1][1] = rl[3];
            }
            #pragma unroll
            for (int mi = 0; mi < 2; ++mi)
                #pragma unroll
                for (int ni = 0; ni < 2; ++ni) {
                    MMA16816(acc[mi][ni], ah[mi], bh[ni]);
                    MMA16816(acc[mi][ni], ah[mi], bl[ni]);
                    MMA16816(acc[mi][ni], al[mi], bh[ni]);
                }
        }
        if (it < nk - 1) {
            int nb = buf ^ 1;
            __syncthreads();
            *(uint2*)(sm + nb * 1536 + aDst + aOff) = vA;
            *(uint2*)(sm + 6144  + nb * 6144 + bOff)  = vBh0;
            *(uint2*)(sm + 6144  + nb * 6144 + bOff2) = vBh1;
            *(uint2*)(sm + 18432 + nb * 6144 + bOff)  = vBl0;
            *(uint2*)(sm + 18432 + nb * 6144 + bOff2) = vBl1;
            __syncthreads();
            buf = nb;
        }
    }
    __syncthreads();   // mainloop buffers dead; overlay sAcc

    const int gr = lane >> 2, gk = (lane & 3) * 2;
    float* sAcc = (float*)sm;
    #pragma unroll
    for (int mi = 0; mi < 2; ++mi) {
        #pragma unroll
        for (int ni = 0; ni < 2; ++ni) {
            int r0 = mi * 16 + gr;
            int c0 = wc * 16 + ni * 8 + gk;
            *(float2*)&sAcc[r0 * 132 + c0]       = make_float2(acc[mi][ni][0], acc[mi][ni][1]);
            *(float2*)&sAcc[(r0 + 8) * 132 + c0] = make_float2(acc[mi][ni][2], acc[mi][ni][3]);
        }
    }
    __syncthreads();
}

// ================= GCN GEMM (mma) + tanh + gate + combine ====================
__global__ __launch_bounds__(256) void gcn_mma(
    const float* __restrict__ wb, const float* __restrict__ gb,
    const float* __restrict__ gate_w, const float* __restrict__ gate_b,
    float* __restrict__ X)
{
    extern __shared__ char sm[];
    const int tid = threadIdx.x;
    const int rowBase = blockIdx.x * 32;
    mma3s_main(sm, g_NAhi, g_NAlo, DMv, 2*NUNIT - 1,
               g_WgcnHi, g_WgcnLo, DMv, rowBase, 0, 16);
    float* sAcc = (float*)sm;

    #pragma unroll
    for (int i = 0; i < 4; ++i) {
        int lin = tid + i * 256;
        int r = lin >> 5, c = (lin & 31) * 4;
        float4 v = *(const float4*)&sAcc[r * 132 + c];
        v.x = tanhf(v.x + wb[c]   + gb[c]);
        v.y = tanhf(v.y + wb[c+1] + gb[c+1]);
        v.z = tanhf(v.z + wb[c+2] + gb[c+2]);
        v.w = tanhf(v.w + wb[c+3] + gb[c+3]);
        *(float4*)&sAcc[r * 132 + c] = v;
    }
    __syncthreads();

    const int t = tid >> 3, sub = tid & 7;
    const int u = (rowBase >> 1) + t;
    if (t < 16 && u < NUNIT) {
        float gv = 0.f;
        #pragma unroll
        for (int k = 0; k < 16; ++k) {
            int c = sub*16 + k;
            gv += sAcc[(2*t) * 132 + c] * gate_w[c] + sAcc[(2*t+1) * 132 + c] * gate_w[128 + c];
        }
        gv += __shfl_xor_sync(0xffffffffu, gv, 1);
        gv += __shfl_xor_sync(0xffffffffu, gv, 2);
        gv += __shfl_xor_sync(0xffffffffu, gv, 4);
        float a = sigm(gv + gate_b[0]);
        int row, col;
        if (u < Bv)             { row = u;                      col = 0; }
        else if (u < 2*Bv)      { row = u - Bv;                 col = Dv; }
        else if (u < 2*Bv+FEWv) { row = Bv + (u - 2*Bv);        col = 0; }
        else                    { row = Bv + (u - 2*Bv - FEWv); col = Dv; }
        size_t xo = (size_t)row * DMv + col;
        #pragma unroll
        for (int k4 = 0; k4 < 4; ++k4) {
            int c = sub*16 + k4*4;
            float4 st = *(const float4*)&sAcc[(2*t) * 132 + c];
            float4 kn = *(const float4*)&sAcc[(2*t+1) * 132 + c];
            float4 o;
            o.x = (1.f - a)*st.x + a*kn.x;
            o.y = (1.f - a)*st.y + a*kn.y;
            o.z = (1.f - a)*st.z + a*kn.z;
            o.w = (1.f - a)*st.w + a*kn.w;
            *(float4*)(X + xo + c) = o;
            split_store4(o, g_XAhi, g_XAlo, xo + c);
        }
    }
}

// ================= p1 GEMM (mma) + relu, emit H splits =======================
__global__ __launch_bounds__(256) void p1_mma(const float* __restrict__ p1_b)
{
    extern __shared__ char sm[];
    const int tid = threadIdx.x;
    const int rowBase = blockIdx.y * 32;
    const int colBase = blockIdx.x * 128;
    mma3s_main(sm, g_XAhi, g_XAlo, DMv, NROWS - 1,
               g_Wp1Hi, g_Wp1Lo, DMv, rowBase, colBase, 16);
    float* sAcc = (float*)sm;
    #pragma unroll
    for (int i = 0; i < 4; ++i) {
        int lin = tid + i * 256;
        int r = lin >> 5, cl = (lin & 31) * 4;
        int row = rowBase + r;
        if (row >= NROWS) continue;
        int c = colBase + cl;
        float4 v = *(const float4*)&sAcc[r * 132 + cl];
        v.x = fmaxf(v.x + p1_b[c],   0.f);
        v.y = fmaxf(v.y + p1_b[c+1], 0.f);
        v.z = fmaxf(v.z + p1_b[c+2], 0.f);
        v.w = fmaxf(v.w + p1_b[c+3], 0.f);
        split_store4(v, g_Hshi, g_Hslo, (size_t)row * HIDv + c);
    }
}

// ================= p2 GEMM (mma) + bias -> O fp32 ============================
__global__ __launch_bounds__(256) void p2_mma(const float* __restrict__ p2_b)
{
    extern __shared__ char sm[];
    const int tid = threadIdx.x;
    const int rowBase = blockIdx.y * 32;
    const int colBase = blockIdx.x * 128;
    mma3s_main(sm, g_Hshi, g_Hslo, HIDv, NROWS - 1,
               g_Wp2Hi, g_Wp2Lo, HIDv, rowBase, colBase, 32);
    float* sAcc = (float*)sm;
    #pragma unroll
    for (int i = 0; i < 4; ++i) {
        int lin = tid + i * 256;
        int r = lin >> 5, cl = (lin & 31) * 4;
        int row = rowBase + r;
        if (row >= NROWS) continue;
        int c = colBase + cl;
        float4 v = *(const float4*)&sAcc[r * 132 + cl];
        v.x += p2_b[c]; v.y += p2_b[c+1]; v.z += p2_b[c+2]; v.w += p2_b[c+3];
        *(float4*)&g_O[(size_t)row * DMv + c] = v;
    }
}

// ================= gate GEMM (mma) + fused LSTM cell =========================
__global__ __launch_bounds__(256) void gates_mma(
    const __nv_bfloat16* __restrict__ Ahi, const __nv_bfloat16* __restrict__ Alo,
    const __nv_bfloat16* __restrict__ Whi, const __nv_bfloat16* __restrict__ Wlo,
    int first)
{
    extern __shared__ char sm[];
    const int tid = threadIdx.x;
    const int rowBase = blockIdx.y * 32;
    const int colBase = blockIdx.x * 128;
    const int jbase = colBase >> 2;
    mma3s_main(sm, Ahi, Alo, DMv, Bv - 1, Whi, Wlo, DMv, rowBase, colBase, 16);
    float* sAcc = (float*)sm;

    #pragma unroll
    for (int i = 0; i < 4; ++i) {
        int lin = tid + i * 256;
        int r = lin >> 5, jl = lin & 31;
        float4 gv = *(const float4*)&sAcc[r * 132 + jl * 4];
        int row = rowBase + r;
        int colp = colBase + jl * 4;
        float gi = gv.x, gf = gv.y, gg = gv.z, go = gv.w;
        size_t g0i = (size_t)row * G4 + colp;
        if (first) {
            gi += g_b4[colp]; gf += g_b4[colp+1]; gg += g_b4[colp+2]; go += g_b4[colp+3];
            *(float4*)&g_G0[g0i] = make_float4(gi, gf, gg, go);
        } else {
            float4 g0 = *(const float4*)&g_G0[g0i];
            gi += g0.x + g_rt4[colp];   gf += g0.y + g_rt4[colp+1];
            gg += g0.z + g_rt4[colp+2]; go += g0.w + g_rt4[colp+3];
        }
        size_t ci = (size_t)row * DMv + jbase + jl;
        float cold = first ? 0.f : g_C[ci];
        float cv = sigm(gf) * cold + sigm(gi) * tanhf(gg);
        g_C[ci] = cv;
        float h = g_X[ci] + sigm(go) * tanhf(cv);
        g_h[ci] = h;
        __nv_bfloat16 hb = __float2bfloat16(h);
        g_hhi[ci] = hb;
        g_hlo[ci] = __float2bfloat16(h - __bfloat162float(hb));
    }
}

// ---------------- residual + layernorm (+ bf16 split emit for query rows) ---
__global__ void posln_kernel(const float* __restrict__ O, float* __restrict__ X,
                             const float* __restrict__ g, const float* __restrict__ b)
{
    __shared__ float s_red[8];
    const int r = blockIdx.x, t = threadIdx.x;
    const int lane = t & 31, w = t >> 5;
    float z = O[(size_t)r * DMv + t] + X[(size_t)r * DMv + t];
    float v = z;
    #pragma unroll
    for (int o = 16; o; o >>= 1) v += __shfl_xor_sync(0xffffffffu, v, o);
    if (lane == 0) s_red[w] = v;
    __syncthreads();
    float mu = 0.f;
    #pragma unroll
    for (int i = 0; i < 8; ++i) mu += s_red[i];
    mu *= (1.f / 256.f);
    __syncthreads();
    float d = z - mu;
    v = d * d;
    #pragma unroll
    for (int o = 16; o; o >>= 1) v += __shfl_xor_sync(0xffffffffu, v, o);
    if (lane == 0) s_red[w] = v;
    __syncthreads();
    float var = 0.f;
    #pragma unroll
    for (int i = 0; i < 8; ++i) var += s_red[i];
    var *= (1.f / 255.f);
    float y = d / (sqrtf(var) + 1e-3f) * g[t] + b[t];
    X[(size_t)r * DMv + t] = y;
    if (r < Bv) {
        __nv_bfloat16 hi = __float2bfloat16(y);
        g_Xhi[(size_t)r * DMv + t] = hi;
        g_Xlo[(size_t)r * DMv + t] = __float2bfloat16(y - __bfloat162float(hi));
    }
}

// ---------------- support_g + l2 normalization ------------------------------
__global__ void sg_kernel(const float* __restrict__ X)
{
    __shared__ float s_red[8];
    const int t = threadIdx.x, lane = t & 31, w = t >> 5;
    float s = 0.f;
    #pragma unroll
    for (int i = 0; i < FEWv; ++i) s += X[(size_t)(Bv + i) * DMv + t];
    s *= (1.f / (float)FEWv);
    g_sg[t] = s;
    float v = s * s;
    #pragma unroll
    for (int o = 16; o; o >>= 1) v += __shfl_xor_sync(0xffffffffu, v, o);
    if (lane == 0) s_red[w] = v;
    __syncthreads();
    float nn = 0.f;
    #pragma unroll
    for (int i = 0; i < 8; ++i) nn += s_red[i];
    g_sgn[t] = s / fmaxf(sqrtf(nn), 1e-12f);
}

// ---------------- rt4[4j+g] = w_hh[g*512+j, 256:512] @ support_g ------------
__global__ void rterm_kernel(const float* __restrict__ w_hh)
{
    const int t = threadIdx.x, lane = t & 31, w = t >> 5;
    const int o = blockIdx.x * 8 + w;
    const int j = o >> 2, gate = o & 3;
    const float* wr = w_hh + (size_t)(gate * 512 + j) * HIDv + DMv;
    float s = 0.f;
    #pragma unroll
    for (int q = 0; q < 8; ++q) s += g_sg[lane + q * 32] * wr[lane + q * 32];
    #pragma unroll
    for (int off = 16; off; off >>= 1) s += __shfl_xor_sync(0xffffffffu, s, off);
    if (lane == 0) g_rt4[o] = s;
}

// ---------------- final cosine against normalized support_g ----------------
__global__ void final_kernel(float* __restrict__ out)
{
    __shared__ float s_red[16];
    const int b = blockIdx.x, t = threadIdx.x, lane = t & 31, w = t >> 5;
    float hv = g_h[(size_t)b * DMv + t];
    float d = hv * g_sgn[t];
    float ss = hv * hv;
    #pragma unroll
    for (int o = 16; o; o >>= 1) {
        d  += __shfl_xor_sync(0xffffffffu, d,  o);
        ss += __shfl_xor_sync(0xffffffffu, ss, o);
    }
    if (lane == 0) { s_red[w] = d; s_red[8 + w] = ss; }
    __syncthreads();
    if (t == 0) {
        float Dd = 0.f, S = 0.f;
        #pragma unroll
        for (int i = 0; i < 8; ++i) { Dd += s_red[i]; S += s_red[8 + i]; }
        out[b] = Dd / fmaxf(sqrtf(S), 1e-12f);
    }
}

// ---------------- launcher ---------------------------------------------------
extern "C" void kernel_launch(void* const* d_in, const int* in_sizes, int n_in,
                              void* d_out, int out_size)
{
    const int*   query    = (const int*)  d_in[0];
    const int*   support  = (const int*)  d_in[1];
    const int*   q_l_conn = (const int*)  d_in[2];
    const int*   q_r_conn = (const int*)  d_in[4];
    const int*   s_l_conn = (const int*)  d_in[6];
    const int*   s_r_conn = (const int*)  d_in[8];
    const int*   knn      = (const int*)  d_in[10];
    const float* emb      = (const float*)d_in[11];
    const float* gcn_w    = (const float*)d_in[12];
    const float* gcn_wb   = (const float*)d_in[13];
    const float* gcn_b    = (const float*)d_in[14];
    const float* gate_w   = (const float*)d_in[15];
    const float* gate_b   = (const float*)d_in[16];
    const float* p1_w     = (const float*)d_in[17];
    const float* p1_b     = (const float*)d_in[18];
    const float* p2_w     = (const float*)d_in[19];
    const float* p2_b     = (const float*)d_in[20];
    const float* ln_g     = (const float*)d_in[21];
    const float* ln_b     = (const float*)d_in[22];
    const float* w_ih     = (const float*)d_in[23];
    const float* w_hh     = (const float*)d_in[24];
    const float* b_ih     = (const float*)d_in[25];
    const float* b_hh     = (const float*)d_in[26];

    float *pX, *pO;
    __nv_bfloat16 *pXhi, *pXlo, *phhi, *phlo, *pWihHi, *pWihLo, *pWhhHi, *pWhhLo;
    cudaGetSymbolAddress((void**)&pX,  g_X);
    cudaGetSymbolAddress((void**)&pO,  g_O);
    cudaGetSymbolAddress((void**)&pXhi, g_Xhi);
    cudaGetSymbolAddress((void**)&pXlo, g_Xlo);
    cudaGetSymbolAddress((void**)&phhi, g_hhi);
    cudaGetSymbolAddress((void**)&phlo, g_hlo);
    cudaGetSymbolAddress((void**)&pWihHi, g_WihHi);
    cudaGetSymbolAddress((void**)&pWihLo, g_WihLo);
    cudaGetSymbolAddress((void**)&pWhhHi, g_WhhHi);
    cudaGetSymbolAddress((void**)&pWhhLo, g_WhhLo);

    // 0) weight packing (independent)
    pack_w<<<G4, 256>>>(w_ih, w_hh, b_ih, b_hh);
    pack_se<<<Dv + HIDv + DMv, 256>>>(gcn_w, p1_w, p2_w);

    // 1) neighbor encoder sims/topk/means -> NA bf16 splits [8212, 256]
    ne_sims<<<NUNIT, 256>>>(query, support, q_l_conn, q_r_conn, s_l_conn, s_r_conn,
                            knn, emb);
    // 2) GCN GEMM (mma/ldmatrix, 32-row tiles) + tanh + gate + combine
    gcn_mma<<<(2*NUNIT + 31)/32, 256, SMEM_MMA>>>(gcn_wb, gcn_b, gate_w, gate_b, pX);

    // 3) support encoder: p1 (mma, relu -> H splits), p2 (mma -> O), LN
    p1_mma<<<dim3(HIDv/128, (NROWS + 31)/32), 256, SMEM_MMA>>>(p1_b);
    p2_mma<<<dim3(DMv/128, (NROWS + 31)/32), 256, SMEM_MMA>>>(p2_b);
    posln_kernel<<<NROWS, 256>>>(pO, pX, ln_g, ln_b);

    // 4) support_g, normalization, reduced interleaved r-term
    sg_kernel<<<1, 256>>>(pX);
    rterm_kernel<<<G4/8, 256>>>(w_hh);

    // 5) LSTM steps on mma.sync bf16 (3x split), fused cell epilogue
    gates_mma<<<dim3(G4/128, Bv/32), 256, SMEM_MMA>>>(pXhi, pXlo, pWihHi, pWihLo, 1);
    for (int s = 0; s < 3; ++s)
        gates_mma<<<dim3(G4/128, Bv/32), 256, SMEM_MMA>>>(phhi, phlo, pWhhHi, pWhhLo, 0);

    // 6) out[b] = l2n(h[b]) . l2n(support_g)
    final_kernel<<<Bv, 256>>>((float*)d_out);

    (void)in_sizes; (void)n_in; (void)out_size;
}